// round 13
// baseline (speedup 1.0000x reference)
#include <cuda_runtime.h>
#include <cuda_bf16.h>
#include <math.h>
#include <stdint.h>

#define S_DIM 4096
#define Q_DIM 4096
#define E_DIM 2048
#define D_DIM 2048
#define CHUNK 2048              /* rows per chain */
#define SUB   1024              /* sub-chunk rows within a chain */

typedef __nv_bfloat16 bf16;

// ---------------------------------------------------------------------------
// Scratch (static device globals — no runtime allocation)
// ---------------------------------------------------------------------------
__device__ bf16 g_q_hi[(size_t)Q_DIM * E_DIM];
__device__ bf16 g_q_lo[(size_t)Q_DIM * E_DIM];
__device__ bf16 g_k_hi[(size_t)S_DIM * E_DIM];
__device__ bf16 g_k_lo[(size_t)S_DIM * E_DIM];
__device__ bf16 g_v_hi[(size_t)S_DIM * E_DIM];
__device__ bf16 g_v_lo[(size_t)S_DIM * E_DIM];
__device__ bf16 g_Wq_hi[(size_t)D_DIM * E_DIM];
__device__ bf16 g_Wq_lo[(size_t)D_DIM * E_DIM];
__device__ bf16 g_Wk_hi[(size_t)D_DIM * E_DIM];
__device__ bf16 g_Wk_lo[(size_t)D_DIM * E_DIM];
__device__ bf16 g_Wv_hi[(size_t)D_DIM * E_DIM];
__device__ bf16 g_Wv_lo[(size_t)D_DIM * E_DIM];
__device__ bf16 g_Qp_hi[(size_t)Q_DIM * D_DIM];
__device__ bf16 g_Qp_lo[(size_t)Q_DIM * D_DIM];
__device__ bf16 g_Kp_hi[(size_t)S_DIM * D_DIM];
__device__ bf16 g_Kp_lo[(size_t)S_DIM * D_DIM];
__device__ bf16 g_VpT_hi[(size_t)D_DIM * S_DIM];  // transposed [D, S]
__device__ bf16 g_VpT_lo[(size_t)D_DIM * S_DIM];
__device__ float g_Sc[(size_t)Q_DIM * S_DIM];
__device__ bf16 g_P_hi[(size_t)Q_DIM * S_DIM];
__device__ bf16 g_P_lo[(size_t)Q_DIM * S_DIM];

// ---------------------------------------------------------------------------
// helpers
// ---------------------------------------------------------------------------
__device__ __forceinline__ uint32_t smem_u32(const void* p) {
    uint32_t a;
    asm("{ .reg .u64 t; cvta.to.shared.u64 t, %1; cvt.u32.u64 %0, t; }"
        : "=r"(a) : "l"(p));
    return a;
}

__device__ __forceinline__ void cp_async16(uint32_t dst, const void* src) {
    asm volatile("cp.async.cg.shared.global [%0], [%1], 16;" :: "r"(dst), "l"(src));
}
#define CP_COMMIT()  asm volatile("cp.async.commit_group;" ::: "memory")
#define CP_WAIT_1()  asm volatile("cp.async.wait_group 1;" ::: "memory")

__device__ __forceinline__ void ldsm_x4(uint32_t& r0, uint32_t& r1, uint32_t& r2, uint32_t& r3,
                                        uint32_t addr) {
    asm volatile("ldmatrix.sync.aligned.m8n8.x4.shared.b16 {%0,%1,%2,%3}, [%4];"
                 : "=r"(r0), "=r"(r1), "=r"(r2), "=r"(r3) : "r"(addr));
}

__device__ __forceinline__ void mma_bf16(float* c, const uint32_t* a, const uint32_t* b) {
    asm volatile(
        "mma.sync.aligned.m16n8k16.row.col.f32.bf16.bf16.f32 "
        "{%0,%1,%2,%3}, {%4,%5,%6,%7}, {%8,%9}, {%0,%1,%2,%3};"
        : "+f"(c[0]), "+f"(c[1]), "+f"(c[2]), "+f"(c[3])
        : "r"(a[0]), "r"(a[1]), "r"(a[2]), "r"(a[3]), "r"(b[0]), "r"(b[1]));
}

__device__ __forceinline__ void split_bf16(float v, bf16& h, bf16& l) {
    h = __float2bfloat16(v);
    l = __float2bfloat16(v - __bfloat162float(h));
}

// warmup no-op (forces lazy per-stream driver resource allocation on call 1)
__global__ void warm_kernel() {}

// ---------------------------------------------------------------------------
// fp32 -> bf16 hi/lo split, 6 arrays in one launch (gridDim.y selects array).
// Even y: nBig elements; odd y: nSmall elements (excess blocks exit).
// ---------------------------------------------------------------------------
__global__ __launch_bounds__(256) void cvt_split6_kernel(
    const float* __restrict__ x0, const float* __restrict__ x1, const float* __restrict__ x2,
    const float* __restrict__ x3, const float* __restrict__ x4, const float* __restrict__ x5,
    bf16* __restrict__ h0, bf16* __restrict__ l0, bf16* __restrict__ h1, bf16* __restrict__ l1,
    bf16* __restrict__ h2, bf16* __restrict__ l2, bf16* __restrict__ h3, bf16* __restrict__ l3,
    bf16* __restrict__ h4, bf16* __restrict__ l4, bf16* __restrict__ h5, bf16* __restrict__ l5,
    size_t nBig, size_t nSmall)
{
    const int y = blockIdx.y;
    const size_t n = (y & 1) ? nSmall : nBig;
    size_t i = ((size_t)blockIdx.x * blockDim.x + threadIdx.x) * 4;
    if (i >= n) return;
    const float* xs[6] = {x0, x1, x2, x3, x4, x5};
    bf16* hs[6] = {h0, h1, h2, h3, h4, h5};
    bf16* ls[6] = {l0, l1, l2, l3, l4, l5};
    const float* x = xs[y];
    bf16* hi = hs[y];
    bf16* lo = ls[y];
    float4 v = *(const float4*)&x[i];
    bf16 a0, b0, a1, b1, a2, b2, a3, b3;
    split_bf16(v.x, a0, b0); split_bf16(v.y, a1, b1);
    split_bf16(v.z, a2, b2); split_bf16(v.w, a3, b3);
    __nv_bfloat162* ph = (__nv_bfloat162*)&hi[i];
    __nv_bfloat162* pl = (__nv_bfloat162*)&lo[i];
    ph[0] = __nv_bfloat162(a0, a1); ph[1] = __nv_bfloat162(a2, a3);
    pl[0] = __nv_bfloat162(b0, b1); pl[1] = __nv_bfloat162(b2, b3);
}

// ---------------------------------------------------------------------------
// bf16x3 GEMM via mma.sync: C[M,N] = (Ah+Al)[M,K] @ (Bh+Bl)[N,K]^T
// MODE 0: C = (acc + bias) * outscale -> Chi/Clo bf16, row-major [M, ldo]
// MODE 1: same, written transposed: Chi/Clo[col * ldo + row]
// MODE 2: C = acc -> Cf fp32 row-major [M, ldo]
// BM=BN=128, BK=32, 3 stages, 256 threads (8 warps 4x2), 2 CTAs/SM.
// ---------------------------------------------------------------------------
#define BK 32
#define NSTAGES 3
#define TILE_B 8192             /* 128 rows x 64 bytes */
#define STAGE_B (4 * TILE_B)    /* 32 KB */
#define SMEM_TOTAL (NSTAGES * STAGE_B)  /* 96 KB */

__device__ __forceinline__ uint32_t sw_off(int row, int chunk) {
    return (uint32_t)(row * 64 + ((chunk ^ ((row >> 1) & 3)) << 4));
}

template <int MODE>
__global__ void __launch_bounds__(256, 2) gemm_bf16x3(
    const bf16* __restrict__ Ah, const bf16* __restrict__ Al,
    const bf16* __restrict__ Bh, const bf16* __restrict__ Bl,
    const float* __restrict__ bias, float outscale,
    bf16* __restrict__ Chi, bf16* __restrict__ Clo, float* __restrict__ Cf,
    int K, int ldo)
{
    extern __shared__ __align__(1024) char smem[];
    const uint32_t sb = smem_u32(smem);
    const int tid  = threadIdx.x;
    const int wid  = tid >> 5;
    const int lane = tid & 31;
    const int bm   = blockIdx.y * 128;
    const int bn   = blockIdx.x * 128;
    const int KT   = K / BK;

    const int warp_m = wid & 3;
    const int warp_n = wid >> 2;
    const int m0 = warp_m * 32;
    const int n0 = warp_n * 64;

    auto load_stage = [&](int kt, int s) {
        const uint32_t sbase = sb + (uint32_t)s * STAGE_B;
        const bf16* srcs[4] = {Ah, Al, Bh, Bl};
#pragma unroll
        for (int t = 0; t < 4; ++t) {
            const int rowbase = (t < 2) ? bm : bn;
            const bf16* gsrc = srcs[t];
            const uint32_t tbase = sbase + (uint32_t)t * TILE_B;
#pragma unroll
            for (int i = 0; i < 2; ++i) {
                const int id = i * 256 + tid;
                const int r = id >> 2;
                const int c = id & 3;
                cp_async16(tbase + sw_off(r, c),
                           gsrc + (size_t)(rowbase + r) * K + kt * BK + c * 8);
            }
        }
        CP_COMMIT();
    };

    float acc[2][8][4];
#pragma unroll
    for (int i = 0; i < 2; ++i)
#pragma unroll
        for (int j = 0; j < 8; ++j)
#pragma unroll
            for (int q = 0; q < 4; ++q) acc[i][j][q] = 0.0f;

    const int a_row = m0 + (lane & 15);
    const int a_ch0 = lane >> 4;
    const int b_row = n0 + (lane & 7) + ((lane >> 4) << 3);
    const int b_ch0 = (lane >> 3) & 1;

    uint32_t a_h[2][4], a_l[2][4];
    uint32_t bA_h[4][2], bA_l[4][2];
    uint32_t bB_h[4][2], bB_l[4][2];

    auto ld_a = [&](uint32_t sbase, int ach) {
#pragma unroll
        for (int mt = 0; mt < 2; ++mt) {
            const uint32_t off = sw_off(a_row + mt * 16, ach);
            ldsm_x4(a_h[mt][0], a_h[mt][1], a_h[mt][2], a_h[mt][3], sbase + off);
            ldsm_x4(a_l[mt][0], a_l[mt][1], a_l[mt][2], a_l[mt][3], sbase + TILE_B + off);
        }
    };
    auto ld_b = [&](uint32_t sbase, int bch, int half, uint32_t (*bh)[2], uint32_t (*bl)[2]) {
        const uint32_t bh_base = sbase + 2 * TILE_B;
        const uint32_t bl_base = sbase + 3 * TILE_B;
#pragma unroll
        for (int jp = 0; jp < 2; ++jp) {
            const uint32_t off = sw_off(b_row + (half * 2 + jp) * 16, bch);
            ldsm_x4(bh[jp * 2][0], bh[jp * 2][1], bh[jp * 2 + 1][0], bh[jp * 2 + 1][1],
                    bh_base + off);
            ldsm_x4(bl[jp * 2][0], bl[jp * 2][1], bl[jp * 2 + 1][0], bl[jp * 2 + 1][1],
                    bl_base + off);
        }
    };
    auto mma24 = [&](int half, uint32_t (*bh)[2], uint32_t (*bl)[2]) {
#pragma unroll
        for (int mt = 0; mt < 2; ++mt)
#pragma unroll
            for (int j = 0; j < 4; ++j) mma_bf16(acc[mt][half * 4 + j], a_h[mt], bh[j]);
#pragma unroll
        for (int mt = 0; mt < 2; ++mt)
#pragma unroll
            for (int j = 0; j < 4; ++j) mma_bf16(acc[mt][half * 4 + j], a_h[mt], bl[j]);
#pragma unroll
        for (int mt = 0; mt < 2; ++mt)
#pragma unroll
            for (int j = 0; j < 4; ++j) mma_bf16(acc[mt][half * 4 + j], a_l[mt], bh[j]);
    };

    load_stage(0, 0);
    load_stage(1, 1);
    CP_WAIT_1();
    __syncthreads();
    {
        const uint32_t s0 = sb;
        ld_b(s0, b_ch0, 0, bA_h, bA_l);
        ld_b(s0, b_ch0, 1, bB_h, bB_l);
        ld_a(s0, a_ch0);
    }

#pragma unroll 1
    for (int kt = 0; kt < KT; ++kt) {
        const uint32_t scur = sb + (uint32_t)((kt % NSTAGES) * STAGE_B);

        if (kt + 2 < KT) load_stage(kt + 2, (kt + 2) % NSTAGES);
        else CP_COMMIT();

        mma24(0, bA_h, bA_l);
        ld_b(scur, 2 + b_ch0, 0, bA_h, bA_l);
        mma24(1, bB_h, bB_l);
        ld_b(scur, 2 + b_ch0, 1, bB_h, bB_l);
        ld_a(scur, 2 + a_ch0);

        CP_WAIT_1();
        __syncthreads();

        if (kt + 1 < KT) {
            const uint32_t snxt = sb + (uint32_t)(((kt + 1) % NSTAGES) * STAGE_B);
            mma24(0, bA_h, bA_l);
            ld_b(snxt, b_ch0, 0, bA_h, bA_l);
            mma24(1, bB_h, bB_l);
            ld_b(snxt, b_ch0, 1, bB_h, bB_l);
            ld_a(snxt, a_ch0);
        } else {
            mma24(0, bA_h, bA_l);
            mma24(1, bB_h, bB_l);
        }
    }

    const int er = lane >> 2;
    const int ec = (lane & 3) * 2;
#pragma unroll
    for (int mt = 0; mt < 2; ++mt) {
#pragma unroll
        for (int j = 0; j < 8; ++j) {
            const int row = bm + m0 + mt * 16 + er;
            const int col = bn + n0 + j * 8 + ec;
            float v0 = acc[mt][j][0], v1 = acc[mt][j][1];
            float v2 = acc[mt][j][2], v3 = acc[mt][j][3];
            if (MODE == 2) {
                *(float2*)&Cf[(size_t)row * ldo + col] = make_float2(v0, v1);
                *(float2*)&Cf[(size_t)(row + 8) * ldo + col] = make_float2(v2, v3);
            } else {
                const float b0 = bias[col], b1 = bias[col + 1];
                v0 = (v0 + b0) * outscale; v1 = (v1 + b1) * outscale;
                v2 = (v2 + b0) * outscale; v3 = (v3 + b1) * outscale;
                bf16 h0, l0, h1, l1, h2, l2, h3, l3;
                split_bf16(v0, h0, l0); split_bf16(v1, h1, l1);
                split_bf16(v2, h2, l2); split_bf16(v3, h3, l3);
                if (MODE == 0) {
                    *(__nv_bfloat162*)&Chi[(size_t)row * ldo + col] = __nv_bfloat162(h0, h1);
                    *(__nv_bfloat162*)&Clo[(size_t)row * ldo + col] = __nv_bfloat162(l0, l1);
                    *(__nv_bfloat162*)&Chi[(size_t)(row + 8) * ldo + col] = __nv_bfloat162(h2, h3);
                    *(__nv_bfloat162*)&Clo[(size_t)(row + 8) * ldo + col] = __nv_bfloat162(l2, l3);
                } else {  // MODE 1: transposed
                    Chi[(size_t)col * ldo + row] = h0;         Clo[(size_t)col * ldo + row] = l0;
                    Chi[(size_t)(col + 1) * ldo + row] = h1;   Clo[(size_t)(col + 1) * ldo + row] = l1;
                    Chi[(size_t)col * ldo + row + 8] = h2;     Clo[(size_t)col * ldo + row + 8] = l2;
                    Chi[(size_t)(col + 1) * ldo + row + 8] = h3; Clo[(size_t)(col + 1) * ldo + row + 8] = l3;
                }
            }
        }
    }
}

// ---------------------------------------------------------------------------
// Row softmax: Sc fp32 [rows, cols] -> P_hi/P_lo bf16
// ---------------------------------------------------------------------------
__global__ __launch_bounds__(256) void softmax_split_kernel(
    float* __restrict__ Sc, bf16* __restrict__ Phi, bf16* __restrict__ Plo, int cols)
{
    __shared__ float red[32];
    const int row = blockIdx.x;
    float* p = Sc + (size_t)row * cols;
    const int tid = threadIdx.x;
    const int lane = tid & 31;
    const int wid = tid >> 5;
    const int nwarp = blockDim.x >> 5;

    float m = -INFINITY;
    for (int i = tid * 4; i < cols; i += blockDim.x * 4) {
        float4 v = *(const float4*)&p[i];
        m = fmaxf(m, fmaxf(fmaxf(v.x, v.y), fmaxf(v.z, v.w)));
    }
#pragma unroll
    for (int o = 16; o > 0; o >>= 1) m = fmaxf(m, __shfl_xor_sync(0xffffffffu, m, o));
    if (lane == 0) red[wid] = m;
    __syncthreads();
    if (wid == 0) {
        float t = (lane < nwarp) ? red[lane] : -INFINITY;
#pragma unroll
        for (int o = 16; o > 0; o >>= 1) t = fmaxf(t, __shfl_xor_sync(0xffffffffu, t, o));
        if (lane == 0) red[0] = t;
    }
    __syncthreads();
    m = red[0];
    __syncthreads();

    float s = 0.0f;
    for (int i = tid * 4; i < cols; i += blockDim.x * 4) {
        float4 v = *(const float4*)&p[i];
        v.x = __expf(v.x - m); v.y = __expf(v.y - m);
        v.z = __expf(v.z - m); v.w = __expf(v.w - m);
        s += v.x + v.y + v.z + v.w;
        *(float4*)&p[i] = v;
    }
#pragma unroll
    for (int o = 16; o > 0; o >>= 1) s += __shfl_xor_sync(0xffffffffu, s, o);
    if (lane == 0) red[wid] = s;
    __syncthreads();
    if (wid == 0) {
        float t = (lane < nwarp) ? red[lane] : 0.0f;
#pragma unroll
        for (int o = 16; o > 0; o >>= 1) t += __shfl_xor_sync(0xffffffffu, t, o);
        if (lane == 0) red[0] = t;
    }
    __syncthreads();
    const float inv = 1.0f / red[0];

    bf16* ph = Phi + (size_t)row * cols;
    bf16* pl = Plo + (size_t)row * cols;
    for (int i = tid * 4; i < cols; i += blockDim.x * 4) {
        float4 v = *(const float4*)&p[i];
        bf16 h0, l0, h1, l1, h2, l2, h3, l3;
        split_bf16(v.x * inv, h0, l0); split_bf16(v.y * inv, h1, l1);
        split_bf16(v.z * inv, h2, l2); split_bf16(v.w * inv, h3, l3);
        __nv_bfloat162* vh = (__nv_bfloat162*)&ph[i];
        __nv_bfloat162* vl = (__nv_bfloat162*)&pl[i];
        vh[0] = __nv_bfloat162(h0, h1); vh[1] = __nv_bfloat162(h2, h3);
        vl[0] = __nv_bfloat162(l0, l1); vl[1] = __nv_bfloat162(l2, l3);
    }
}

// ---------------------------------------------------------------------------
// Host: round-10 topology (3 streams + 5 events, each recorded once) with
// fused cvt and sub-chunked chains. Resources created once on call 1.
// ---------------------------------------------------------------------------
extern "C" void kernel_launch(void* const* d_in, const int* in_sizes, int n_in,
                              void* d_out, int out_size)
{
    const float* key   = (const float*)d_in[0];
    const float* value = (const float*)d_in[1];
    const float* query = (const float*)d_in[2];
    const float* Wk    = (const float*)d_in[3];
    const float* bk    = (const float*)d_in[4];
    const float* Wq    = (const float*)d_in[5];
    const float* bq    = (const float*)d_in[6];
    const float* Wv    = (const float*)d_in[7];
    const float* bv    = (const float*)d_in[8];
    float* out = (float*)d_out;

    void *q_hi_, *q_lo_, *k_hi_, *k_lo_, *v_hi_, *v_lo_;
    void *Wq_hi_, *Wq_lo_, *Wk_hi_, *Wk_lo_, *Wv_hi_, *Wv_lo_;
    void *Qp_hi_, *Qp_lo_, *Kp_hi_, *Kp_lo_, *VpT_hi_, *VpT_lo_;
    void *Sc_, *P_hi_, *P_lo_;
    cudaGetSymbolAddress(&q_hi_, g_q_hi);   cudaGetSymbolAddress(&q_lo_, g_q_lo);
    cudaGetSymbolAddress(&k_hi_, g_k_hi);   cudaGetSymbolAddress(&k_lo_, g_k_lo);
    cudaGetSymbolAddress(&v_hi_, g_v_hi);   cudaGetSymbolAddress(&v_lo_, g_v_lo);
    cudaGetSymbolAddress(&Wq_hi_, g_Wq_hi); cudaGetSymbolAddress(&Wq_lo_, g_Wq_lo);
    cudaGetSymbolAddress(&Wk_hi_, g_Wk_hi); cudaGetSymbolAddress(&Wk_lo_, g_Wk_lo);
    cudaGetSymbolAddress(&Wv_hi_, g_Wv_hi); cudaGetSymbolAddress(&Wv_lo_, g_Wv_lo);
    cudaGetSymbolAddress(&Qp_hi_, g_Qp_hi); cudaGetSymbolAddress(&Qp_lo_, g_Qp_lo);
    cudaGetSymbolAddress(&Kp_hi_, g_Kp_hi); cudaGetSymbolAddress(&Kp_lo_, g_Kp_lo);
    cudaGetSymbolAddress(&VpT_hi_, g_VpT_hi); cudaGetSymbolAddress(&VpT_lo_, g_VpT_lo);
    cudaGetSymbolAddress(&Sc_, g_Sc);
    cudaGetSymbolAddress(&P_hi_, g_P_hi);   cudaGetSymbolAddress(&P_lo_, g_P_lo);

    bf16 *q_hi = (bf16*)q_hi_, *q_lo = (bf16*)q_lo_;
    bf16 *k_hi = (bf16*)k_hi_, *k_lo = (bf16*)k_lo_;
    bf16 *v_hi = (bf16*)v_hi_, *v_lo = (bf16*)v_lo_;
    bf16 *Wq_hi = (bf16*)Wq_hi_, *Wq_lo = (bf16*)Wq_lo_;
    bf16 *Wk_hi = (bf16*)Wk_hi_, *Wk_lo = (bf16*)Wk_lo_;
    bf16 *Wv_hi = (bf16*)Wv_hi_, *Wv_lo = (bf16*)Wv_lo_;
    bf16 *Qp_hi = (bf16*)Qp_hi_, *Qp_lo = (bf16*)Qp_lo_;
    bf16 *Kp_hi = (bf16*)Kp_hi_, *Kp_lo = (bf16*)Kp_lo_;
    bf16 *VpT_hi = (bf16*)VpT_hi_, *VpT_lo = (bf16*)VpT_lo_;
    float *Sc = (float*)Sc_;
    bf16 *P_hi = (bf16*)P_hi_, *P_lo = (bf16*)P_lo_;

    // One-time resource setup (correctness run); reused during capture.
    static bool s_inited = false;
    static cudaStream_t sA, sB, sC;
    static cudaEvent_t eCvt, eK, eV, eA, eB;
    if (!s_inited) {
        cudaFuncSetAttribute(gemm_bf16x3<0>, cudaFuncAttributeMaxDynamicSharedMemorySize, SMEM_TOTAL);
        cudaFuncSetAttribute(gemm_bf16x3<1>, cudaFuncAttributeMaxDynamicSharedMemorySize, SMEM_TOTAL);
        cudaFuncSetAttribute(gemm_bf16x3<2>, cudaFuncAttributeMaxDynamicSharedMemorySize, SMEM_TOTAL);
        cudaStreamCreateWithFlags(&sA, cudaStreamNonBlocking);
        cudaStreamCreateWithFlags(&sB, cudaStreamNonBlocking);
        cudaStreamCreateWithFlags(&sC, cudaStreamNonBlocking);
        cudaEventCreateWithFlags(&eCvt, cudaEventDisableTiming);
        cudaEventCreateWithFlags(&eK, cudaEventDisableTiming);
        cudaEventCreateWithFlags(&eV, cudaEventDisableTiming);
        cudaEventCreateWithFlags(&eA, cudaEventDisableTiming);
        cudaEventCreateWithFlags(&eB, cudaEventDisableTiming);
        // Warm streams/events so lazy driver allocations happen NOW.
        cudaEventRecord(eCvt, 0);
        cudaStreamWaitEvent(sA, eCvt, 0);
        cudaStreamWaitEvent(sB, eCvt, 0);
        cudaStreamWaitEvent(sC, eCvt, 0);
        warm_kernel<<<1, 32, 0, sA>>>();
        warm_kernel<<<1, 32, 0, sB>>>();
        warm_kernel<<<1, 32, 0, sC>>>();
        cudaEventRecord(eA, sA); cudaEventRecord(eB, sB); cudaEventRecord(eV, sC);
        cudaStreamWaitEvent(0, eA, 0);
        cudaStreamWaitEvent(0, eB, 0);
        cudaStreamWaitEvent(0, eV, 0);
        cudaEventRecord(eK, 0);
        s_inited = true;
    }

    const float scale = 1.0f / sqrtf((float)D_DIM);
    const size_t nQE = (size_t)Q_DIM * E_DIM;   // 8M
    const size_t nDE = (size_t)D_DIM * E_DIM;   // 4M

    // ---- 1. cvt fused: all six arrays, one launch on main stream ----
    cvt_split6_kernel<<<dim3((unsigned)(nQE / 1024), 6), 256>>>(
        query, Wq, key, Wk, value, Wv,
        q_hi, q_lo, Wq_hi, Wq_lo,
        k_hi, k_lo, Wk_hi, Wk_lo,
        v_hi, v_lo, Wv_hi, Wv_lo,
        nQE, nDE);
    cudaEventRecord(eCvt, 0);

    // ---- 2. projK on main stream (gates all scores; launched first) ----
    gemm_bf16x3<0><<<dim3(D_DIM / 128, S_DIM / 128), 256, SMEM_TOTAL>>>(
        k_hi, k_lo, Wk_hi, Wk_lo, bk, 1.0f, Kp_hi, Kp_lo, nullptr, E_DIM, D_DIM);
    cudaEventRecord(eK, 0);

    // ---- 3. projV on sC (records eV: out-GEMM gate) ----
    cudaStreamWaitEvent(sC, eCvt, 0);
    gemm_bf16x3<1><<<dim3(D_DIM / 128, S_DIM / 128), 256, SMEM_TOTAL, sC>>>(
        v_hi, v_lo, Wv_hi, Wv_lo, bv, 1.0f, VpT_hi, VpT_lo, nullptr, E_DIM, S_DIM);
    cudaEventRecord(eV, sC);

    // ---- 4. two chains (sA, sB), each sub-chunked into 2x1024 rows ----
    cudaStream_t chains[2] = {sA, sB};
    cudaEvent_t  eDone[2] = {eA, eB};
    for (int c = 0; c < 2; ++c) {
        cudaStream_t st = chains[c];
        const size_t ro = (size_t)c * CHUNK;

        cudaStreamWaitEvent(st, eCvt, 0);
        // projQ for the full chain (2048 rows)
        gemm_bf16x3<0><<<dim3(D_DIM / 128, CHUNK / 128), 256, SMEM_TOTAL, st>>>(
            q_hi + ro * E_DIM, q_lo + ro * E_DIM, Wq_hi, Wq_lo,
            bq, scale, Qp_hi + ro * D_DIM, Qp_lo + ro * D_DIM, nullptr, E_DIM, D_DIM);

        cudaStreamWaitEvent(st, eK, 0);
        cudaStreamWaitEvent(st, eV, 0);   // satisfied early; gates outs below

        for (int s = 0; s < 2; ++s) {
            const size_t so = ro + (size_t)s * SUB;
            // scores sub-chunk
            gemm_bf16x3<2><<<dim3(S_DIM / 128, SUB / 128), 256, SMEM_TOTAL, st>>>(
                Qp_hi + so * D_DIM, Qp_lo + so * D_DIM, Kp_hi, Kp_lo,
                nullptr, 1.0f, nullptr, nullptr, Sc + so * S_DIM, D_DIM, S_DIM);
            // softmax sub-chunk
            softmax_split_kernel<<<SUB, 256, 0, st>>>(
                Sc + so * S_DIM, P_hi + so * S_DIM, P_lo + so * S_DIM, S_DIM);
            // out sub-chunk (eV already waited on this stream)
            gemm_bf16x3<2><<<dim3(D_DIM / 128, SUB / 128), 256, SMEM_TOTAL, st>>>(
                P_hi + so * S_DIM, P_lo + so * S_DIM, VpT_hi, VpT_lo,
                nullptr, 1.0f, nullptr, nullptr, out + so * D_DIM, S_DIM, D_DIM);
        }
        cudaEventRecord(eDone[c], st);
    }

    // ---- 5. join back to main stream ----
    cudaStreamWaitEvent(0, eA, 0);
    cudaStreamWaitEvent(0, eB, 0);
}

// round 14
// speedup vs baseline: 1.0843x; 1.0843x over previous
#include <cuda_runtime.h>
#include <cuda_bf16.h>
#include <math.h>
#include <stdint.h>

#define S_DIM 4096
#define Q_DIM 4096
#define E_DIM 2048
#define D_DIM 2048
#define CHUNK 2048              /* rows per chain */
#define SUB   1024              /* sub-chunk rows within a chain */

typedef __nv_bfloat16 bf16;

// ---------------------------------------------------------------------------
// Scratch (static device globals — no runtime allocation)
// ---------------------------------------------------------------------------
__device__ bf16 g_q_hi[(size_t)Q_DIM * E_DIM];
__device__ bf16 g_q_lo[(size_t)Q_DIM * E_DIM];
__device__ bf16 g_k_hi[(size_t)S_DIM * E_DIM];
__device__ bf16 g_k_lo[(size_t)S_DIM * E_DIM];
__device__ bf16 g_v_hi[(size_t)S_DIM * E_DIM];
__device__ bf16 g_v_lo[(size_t)S_DIM * E_DIM];
__device__ bf16 g_Wq_hi[(size_t)D_DIM * E_DIM];
__device__ bf16 g_Wq_lo[(size_t)D_DIM * E_DIM];
__device__ bf16 g_Wk_hi[(size_t)D_DIM * E_DIM];
__device__ bf16 g_Wk_lo[(size_t)D_DIM * E_DIM];
__device__ bf16 g_Wv_hi[(size_t)D_DIM * E_DIM];
__device__ bf16 g_Wv_lo[(size_t)D_DIM * E_DIM];
__device__ bf16 g_Qp_hi[(size_t)Q_DIM * D_DIM];
__device__ bf16 g_Qp_lo[(size_t)Q_DIM * D_DIM];
__device__ bf16 g_Kp_hi[(size_t)S_DIM * D_DIM];
__device__ bf16 g_Kp_lo[(size_t)S_DIM * D_DIM];
__device__ bf16 g_VpT_hi[(size_t)D_DIM * S_DIM];  // transposed [D, S]
__device__ bf16 g_VpT_lo[(size_t)D_DIM * S_DIM];
__device__ float g_Sc[(size_t)Q_DIM * S_DIM];
__device__ bf16 g_P_hi[(size_t)Q_DIM * S_DIM];
__device__ bf16 g_P_lo[(size_t)Q_DIM * S_DIM];

// ---------------------------------------------------------------------------
// helpers
// ---------------------------------------------------------------------------
__device__ __forceinline__ uint32_t smem_u32(const void* p) {
    uint32_t a;
    asm("{ .reg .u64 t; cvta.to.shared.u64 t, %1; cvt.u32.u64 %0, t; }"
        : "=r"(a) : "l"(p));
    return a;
}

__device__ __forceinline__ void cp_async16(uint32_t dst, const void* src) {
    asm volatile("cp.async.cg.shared.global [%0], [%1], 16;" :: "r"(dst), "l"(src));
}
#define CP_COMMIT()  asm volatile("cp.async.commit_group;" ::: "memory")
#define CP_WAIT_1()  asm volatile("cp.async.wait_group 1;" ::: "memory")

__device__ __forceinline__ void ldsm_x4(uint32_t& r0, uint32_t& r1, uint32_t& r2, uint32_t& r3,
                                        uint32_t addr) {
    asm volatile("ldmatrix.sync.aligned.m8n8.x4.shared.b16 {%0,%1,%2,%3}, [%4];"
                 : "=r"(r0), "=r"(r1), "=r"(r2), "=r"(r3) : "r"(addr));
}

__device__ __forceinline__ void mma_bf16(float* c, const uint32_t* a, const uint32_t* b) {
    asm volatile(
        "mma.sync.aligned.m16n8k16.row.col.f32.bf16.bf16.f32 "
        "{%0,%1,%2,%3}, {%4,%5,%6,%7}, {%8,%9}, {%0,%1,%2,%3};"
        : "+f"(c[0]), "+f"(c[1]), "+f"(c[2]), "+f"(c[3])
        : "r"(a[0]), "r"(a[1]), "r"(a[2]), "r"(a[3]), "r"(b[0]), "r"(b[1]));
}

__device__ __forceinline__ void split_bf16(float v, bf16& h, bf16& l) {
    h = __float2bfloat16(v);
    l = __float2bfloat16(v - __bfloat162float(h));
}

// warmup no-op (forces lazy per-stream driver resource allocation on call 1)
__global__ void warm_kernel() {}

// ---------------------------------------------------------------------------
// fp32 -> bf16 hi/lo split, 3 arrays per launch (ternary pointer selection
// compiles to predicated selects — NO local-memory pointer arrays).
// ---------------------------------------------------------------------------
__global__ __launch_bounds__(256) void cvt_split3_kernel(
    const float* __restrict__ x0, const float* __restrict__ x1, const float* __restrict__ x2,
    bf16* __restrict__ h0, bf16* __restrict__ l0,
    bf16* __restrict__ h1, bf16* __restrict__ l1,
    bf16* __restrict__ h2, bf16* __restrict__ l2, size_t n)
{
    const float* x = (blockIdx.y == 0) ? x0 : (blockIdx.y == 1) ? x1 : x2;
    bf16* hi = (blockIdx.y == 0) ? h0 : (blockIdx.y == 1) ? h1 : h2;
    bf16* lo = (blockIdx.y == 0) ? l0 : (blockIdx.y == 1) ? l1 : l2;
    size_t i = ((size_t)blockIdx.x * blockDim.x + threadIdx.x) * 4;
    if (i >= n) return;
    float4 v = *(const float4*)&x[i];
    bf16 a0, b0, a1, b1, a2, b2, a3, b3;
    split_bf16(v.x, a0, b0); split_bf16(v.y, a1, b1);
    split_bf16(v.z, a2, b2); split_bf16(v.w, a3, b3);
    __nv_bfloat162* ph = (__nv_bfloat162*)&hi[i];
    __nv_bfloat162* pl = (__nv_bfloat162*)&lo[i];
    ph[0] = __nv_bfloat162(a0, a1); ph[1] = __nv_bfloat162(a2, a3);
    pl[0] = __nv_bfloat162(b0, b1); pl[1] = __nv_bfloat162(b2, b3);
}

// ---------------------------------------------------------------------------
// bf16x3 GEMM via mma.sync: C[M,N] = (Ah+Al)[M,K] @ (Bh+Bl)[N,K]^T
// MODE 0: C = (acc + bias) * outscale -> Chi/Clo bf16, row-major [M, ldo]
// MODE 1: same, written transposed: Chi/Clo[col * ldo + row]
// MODE 2: C = acc -> Cf fp32 row-major [M, ldo]
// BM=BN=128, BK=32, 3 stages, 256 threads (8 warps 4x2), 2 CTAs/SM.
// ---------------------------------------------------------------------------
#define BK 32
#define NSTAGES 3
#define TILE_B 8192             /* 128 rows x 64 bytes */
#define STAGE_B (4 * TILE_B)    /* 32 KB */
#define SMEM_TOTAL (NSTAGES * STAGE_B)  /* 96 KB */

__device__ __forceinline__ uint32_t sw_off(int row, int chunk) {
    return (uint32_t)(row * 64 + ((chunk ^ ((row >> 1) & 3)) << 4));
}

template <int MODE>
__global__ void __launch_bounds__(256, 2) gemm_bf16x3(
    const bf16* __restrict__ Ah, const bf16* __restrict__ Al,
    const bf16* __restrict__ Bh, const bf16* __restrict__ Bl,
    const float* __restrict__ bias, float outscale,
    bf16* __restrict__ Chi, bf16* __restrict__ Clo, float* __restrict__ Cf,
    int K, int ldo)
{
    extern __shared__ __align__(1024) char smem[];
    const uint32_t sb = smem_u32(smem);
    const int tid  = threadIdx.x;
    const int wid  = tid >> 5;
    const int lane = tid & 31;
    const int bm   = blockIdx.y * 128;
    const int bn   = blockIdx.x * 128;
    const int KT   = K / BK;

    const int warp_m = wid & 3;
    const int warp_n = wid >> 2;
    const int m0 = warp_m * 32;
    const int n0 = warp_n * 64;

    auto load_stage = [&](int kt, int s) {
        const uint32_t sbase = sb + (uint32_t)s * STAGE_B;
        const bf16* srcs[4] = {Ah, Al, Bh, Bl};
#pragma unroll
        for (int t = 0; t < 4; ++t) {
            const int rowbase = (t < 2) ? bm : bn;
            const bf16* gsrc = srcs[t];
            const uint32_t tbase = sbase + (uint32_t)t * TILE_B;
#pragma unroll
            for (int i = 0; i < 2; ++i) {
                const int id = i * 256 + tid;
                const int r = id >> 2;
                const int c = id & 3;
                cp_async16(tbase + sw_off(r, c),
                           gsrc + (size_t)(rowbase + r) * K + kt * BK + c * 8);
            }
        }
        CP_COMMIT();
    };

    float acc[2][8][4];
#pragma unroll
    for (int i = 0; i < 2; ++i)
#pragma unroll
        for (int j = 0; j < 8; ++j)
#pragma unroll
            for (int q = 0; q < 4; ++q) acc[i][j][q] = 0.0f;

    const int a_row = m0 + (lane & 15);
    const int a_ch0 = lane >> 4;
    const int b_row = n0 + (lane & 7) + ((lane >> 4) << 3);
    const int b_ch0 = (lane >> 3) & 1;

    uint32_t a_h[2][4], a_l[2][4];
    uint32_t bA_h[4][2], bA_l[4][2];
    uint32_t bB_h[4][2], bB_l[4][2];

    auto ld_a = [&](uint32_t sbase, int ach) {
#pragma unroll
        for (int mt = 0; mt < 2; ++mt) {
            const uint32_t off = sw_off(a_row + mt * 16, ach);
            ldsm_x4(a_h[mt][0], a_h[mt][1], a_h[mt][2], a_h[mt][3], sbase + off);
            ldsm_x4(a_l[mt][0], a_l[mt][1], a_l[mt][2], a_l[mt][3], sbase + TILE_B + off);
        }
    };
    auto ld_b = [&](uint32_t sbase, int bch, int half, uint32_t (*bh)[2], uint32_t (*bl)[2]) {
        const uint32_t bh_base = sbase + 2 * TILE_B;
        const uint32_t bl_base = sbase + 3 * TILE_B;
#pragma unroll
        for (int jp = 0; jp < 2; ++jp) {
            const uint32_t off = sw_off(b_row + (half * 2 + jp) * 16, bch);
            ldsm_x4(bh[jp * 2][0], bh[jp * 2][1], bh[jp * 2 + 1][0], bh[jp * 2 + 1][1],
                    bh_base + off);
            ldsm_x4(bl[jp * 2][0], bl[jp * 2][1], bl[jp * 2 + 1][0], bl[jp * 2 + 1][1],
                    bl_base + off);
        }
    };
    auto mma24 = [&](int half, uint32_t (*bh)[2], uint32_t (*bl)[2]) {
#pragma unroll
        for (int mt = 0; mt < 2; ++mt)
#pragma unroll
            for (int j = 0; j < 4; ++j) mma_bf16(acc[mt][half * 4 + j], a_h[mt], bh[j]);
#pragma unroll
        for (int mt = 0; mt < 2; ++mt)
#pragma unroll
            for (int j = 0; j < 4; ++j) mma_bf16(acc[mt][half * 4 + j], a_h[mt], bl[j]);
#pragma unroll
        for (int mt = 0; mt < 2; ++mt)
#pragma unroll
            for (int j = 0; j < 4; ++j) mma_bf16(acc[mt][half * 4 + j], a_l[mt], bh[j]);
    };

    load_stage(0, 0);
    load_stage(1, 1);
    CP_WAIT_1();
    __syncthreads();
    {
        const uint32_t s0 = sb;
        ld_b(s0, b_ch0, 0, bA_h, bA_l);
        ld_b(s0, b_ch0, 1, bB_h, bB_l);
        ld_a(s0, a_ch0);
    }

#pragma unroll 1
    for (int kt = 0; kt < KT; ++kt) {
        const uint32_t scur = sb + (uint32_t)((kt % NSTAGES) * STAGE_B);

        if (kt + 2 < KT) load_stage(kt + 2, (kt + 2) % NSTAGES);
        else CP_COMMIT();

        mma24(0, bA_h, bA_l);
        ld_b(scur, 2 + b_ch0, 0, bA_h, bA_l);
        mma24(1, bB_h, bB_l);
        ld_b(scur, 2 + b_ch0, 1, bB_h, bB_l);
        ld_a(scur, 2 + a_ch0);

        CP_WAIT_1();
        __syncthreads();

        if (kt + 1 < KT) {
            const uint32_t snxt = sb + (uint32_t)(((kt + 1) % NSTAGES) * STAGE_B);
            mma24(0, bA_h, bA_l);
            ld_b(snxt, b_ch0, 0, bA_h, bA_l);
            mma24(1, bB_h, bB_l);
            ld_b(snxt, b_ch0, 1, bB_h, bB_l);
            ld_a(snxt, a_ch0);
        } else {
            mma24(0, bA_h, bA_l);
            mma24(1, bB_h, bB_l);
        }
    }

    const int er = lane >> 2;
    const int ec = (lane & 3) * 2;
#pragma unroll
    for (int mt = 0; mt < 2; ++mt) {
#pragma unroll
        for (int j = 0; j < 8; ++j) {
            const int row = bm + m0 + mt * 16 + er;
            const int col = bn + n0 + j * 8 + ec;
            float v0 = acc[mt][j][0], v1 = acc[mt][j][1];
            float v2 = acc[mt][j][2], v3 = acc[mt][j][3];
            if (MODE == 2) {
                *(float2*)&Cf[(size_t)row * ldo + col] = make_float2(v0, v1);
                *(float2*)&Cf[(size_t)(row + 8) * ldo + col] = make_float2(v2, v3);
            } else {
                const float b0 = bias[col], b1 = bias[col + 1];
                v0 = (v0 + b0) * outscale; v1 = (v1 + b1) * outscale;
                v2 = (v2 + b0) * outscale; v3 = (v3 + b1) * outscale;
                bf16 h0, l0, h1, l1, h2, l2, h3, l3;
                split_bf16(v0, h0, l0); split_bf16(v1, h1, l1);
                split_bf16(v2, h2, l2); split_bf16(v3, h3, l3);
                if (MODE == 0) {
                    *(__nv_bfloat162*)&Chi[(size_t)row * ldo + col] = __nv_bfloat162(h0, h1);
                    *(__nv_bfloat162*)&Clo[(size_t)row * ldo + col] = __nv_bfloat162(l0, l1);
                    *(__nv_bfloat162*)&Chi[(size_t)(row + 8) * ldo + col] = __nv_bfloat162(h2, h3);
                    *(__nv_bfloat162*)&Clo[(size_t)(row + 8) * ldo + col] = __nv_bfloat162(l2, l3);
                } else {  // MODE 1: transposed
                    Chi[(size_t)col * ldo + row] = h0;         Clo[(size_t)col * ldo + row] = l0;
                    Chi[(size_t)(col + 1) * ldo + row] = h1;   Clo[(size_t)(col + 1) * ldo + row] = l1;
                    Chi[(size_t)col * ldo + row + 8] = h2;     Clo[(size_t)col * ldo + row + 8] = l2;
                    Chi[(size_t)(col + 1) * ldo + row + 8] = h3; Clo[(size_t)(col + 1) * ldo + row + 8] = l3;
                }
            }
        }
    }
}

// ---------------------------------------------------------------------------
// Row softmax: Sc fp32 [rows, cols] -> P_hi/P_lo bf16
// ---------------------------------------------------------------------------
__global__ __launch_bounds__(256) void softmax_split_kernel(
    float* __restrict__ Sc, bf16* __restrict__ Phi, bf16* __restrict__ Plo, int cols)
{
    __shared__ float red[32];
    const int row = blockIdx.x;
    float* p = Sc + (size_t)row * cols;
    const int tid = threadIdx.x;
    const int lane = tid & 31;
    const int wid = tid >> 5;
    const int nwarp = blockDim.x >> 5;

    float m = -INFINITY;
    for (int i = tid * 4; i < cols; i += blockDim.x * 4) {
        float4 v = *(const float4*)&p[i];
        m = fmaxf(m, fmaxf(fmaxf(v.x, v.y), fmaxf(v.z, v.w)));
    }
#pragma unroll
    for (int o = 16; o > 0; o >>= 1) m = fmaxf(m, __shfl_xor_sync(0xffffffffu, m, o));
    if (lane == 0) red[wid] = m;
    __syncthreads();
    if (wid == 0) {
        float t = (lane < nwarp) ? red[lane] : -INFINITY;
#pragma unroll
        for (int o = 16; o > 0; o >>= 1) t = fmaxf(t, __shfl_xor_sync(0xffffffffu, t, o));
        if (lane == 0) red[0] = t;
    }
    __syncthreads();
    m = red[0];
    __syncthreads();

    float s = 0.0f;
    for (int i = tid * 4; i < cols; i += blockDim.x * 4) {
        float4 v = *(const float4*)&p[i];
        v.x = __expf(v.x - m); v.y = __expf(v.y - m);
        v.z = __expf(v.z - m); v.w = __expf(v.w - m);
        s += v.x + v.y + v.z + v.w;
        *(float4*)&p[i] = v;
    }
#pragma unroll
    for (int o = 16; o > 0; o >>= 1) s += __shfl_xor_sync(0xffffffffu, s, o);
    if (lane == 0) red[wid] = s;
    __syncthreads();
    if (wid == 0) {
        float t = (lane < nwarp) ? red[lane] : 0.0f;
#pragma unroll
        for (int o = 16; o > 0; o >>= 1) t += __shfl_xor_sync(0xffffffffu, t, o);
        if (lane == 0) red[0] = t;
    }
    __syncthreads();
    const float inv = 1.0f / red[0];

    bf16* ph = Phi + (size_t)row * cols;
    bf16* pl = Plo + (size_t)row * cols;
    for (int i = tid * 4; i < cols; i += blockDim.x * 4) {
        float4 v = *(const float4*)&p[i];
        bf16 h0, l0, h1, l1, h2, l2, h3, l3;
        split_bf16(v.x * inv, h0, l0); split_bf16(v.y * inv, h1, l1);
        split_bf16(v.z * inv, h2, l2); split_bf16(v.w * inv, h3, l3);
        __nv_bfloat162* vh = (__nv_bfloat162*)&ph[i];
        __nv_bfloat162* vl = (__nv_bfloat162*)&pl[i];
        vh[0] = __nv_bfloat162(h0, h1); vh[1] = __nv_bfloat162(h2, h3);
        vl[0] = __nv_bfloat162(l0, l1); vl[1] = __nv_bfloat162(l2, l3);
    }
}

// ---------------------------------------------------------------------------
// Host: round-10 topology (3 streams + 5 events, each recorded once) with
// sub-chunked chains. cvt back to the proven 2x cvt_split3 launches.
// ---------------------------------------------------------------------------
extern "C" void kernel_launch(void* const* d_in, const int* in_sizes, int n_in,
                              void* d_out, int out_size)
{
    const float* key   = (const float*)d_in[0];
    const float* value = (const float*)d_in[1];
    const float* query = (const float*)d_in[2];
    const float* Wk    = (const float*)d_in[3];
    const float* bk    = (const float*)d_in[4];
    const float* Wq    = (const float*)d_in[5];
    const float* bq    = (const float*)d_in[6];
    const float* Wv    = (const float*)d_in[7];
    const float* bv    = (const float*)d_in[8];
    float* out = (float*)d_out;

    void *q_hi_, *q_lo_, *k_hi_, *k_lo_, *v_hi_, *v_lo_;
    void *Wq_hi_, *Wq_lo_, *Wk_hi_, *Wk_lo_, *Wv_hi_, *Wv_lo_;
    void *Qp_hi_, *Qp_lo_, *Kp_hi_, *Kp_lo_, *VpT_hi_, *VpT_lo_;
    void *Sc_, *P_hi_, *P_lo_;
    cudaGetSymbolAddress(&q_hi_, g_q_hi);   cudaGetSymbolAddress(&q_lo_, g_q_lo);
    cudaGetSymbolAddress(&k_hi_, g_k_hi);   cudaGetSymbolAddress(&k_lo_, g_k_lo);
    cudaGetSymbolAddress(&v_hi_, g_v_hi);   cudaGetSymbolAddress(&v_lo_, g_v_lo);
    cudaGetSymbolAddress(&Wq_hi_, g_Wq_hi); cudaGetSymbolAddress(&Wq_lo_, g_Wq_lo);
    cudaGetSymbolAddress(&Wk_hi_, g_Wk_hi); cudaGetSymbolAddress(&Wk_lo_, g_Wk_lo);
    cudaGetSymbolAddress(&Wv_hi_, g_Wv_hi); cudaGetSymbolAddress(&Wv_lo_, g_Wv_lo);
    cudaGetSymbolAddress(&Qp_hi_, g_Qp_hi); cudaGetSymbolAddress(&Qp_lo_, g_Qp_lo);
    cudaGetSymbolAddress(&Kp_hi_, g_Kp_hi); cudaGetSymbolAddress(&Kp_lo_, g_Kp_lo);
    cudaGetSymbolAddress(&VpT_hi_, g_VpT_hi); cudaGetSymbolAddress(&VpT_lo_, g_VpT_lo);
    cudaGetSymbolAddress(&Sc_, g_Sc);
    cudaGetSymbolAddress(&P_hi_, g_P_hi);   cudaGetSymbolAddress(&P_lo_, g_P_lo);

    bf16 *q_hi = (bf16*)q_hi_, *q_lo = (bf16*)q_lo_;
    bf16 *k_hi = (bf16*)k_hi_, *k_lo = (bf16*)k_lo_;
    bf16 *v_hi = (bf16*)v_hi_, *v_lo = (bf16*)v_lo_;
    bf16 *Wq_hi = (bf16*)Wq_hi_, *Wq_lo = (bf16*)Wq_lo_;
    bf16 *Wk_hi = (bf16*)Wk_hi_, *Wk_lo = (bf16*)Wk_lo_;
    bf16 *Wv_hi = (bf16*)Wv_hi_, *Wv_lo = (bf16*)Wv_lo_;
    bf16 *Qp_hi = (bf16*)Qp_hi_, *Qp_lo = (bf16*)Qp_lo_;
    bf16 *Kp_hi = (bf16*)Kp_hi_, *Kp_lo = (bf16*)Kp_lo_;
    bf16 *VpT_hi = (bf16*)VpT_hi_, *VpT_lo = (bf16*)VpT_lo_;
    float *Sc = (float*)Sc_;
    bf16 *P_hi = (bf16*)P_hi_, *P_lo = (bf16*)P_lo_;

    // One-time resource setup (correctness run); reused during capture.
    static bool s_inited = false;
    static cudaStream_t sA, sB, sC;
    static cudaEvent_t eCvt, eK, eV, eA, eB;
    if (!s_inited) {
        cudaFuncSetAttribute(gemm_bf16x3<0>, cudaFuncAttributeMaxDynamicSharedMemorySize, SMEM_TOTAL);
        cudaFuncSetAttribute(gemm_bf16x3<1>, cudaFuncAttributeMaxDynamicSharedMemorySize, SMEM_TOTAL);
        cudaFuncSetAttribute(gemm_bf16x3<2>, cudaFuncAttributeMaxDynamicSharedMemorySize, SMEM_TOTAL);
        cudaStreamCreateWithFlags(&sA, cudaStreamNonBlocking);
        cudaStreamCreateWithFlags(&sB, cudaStreamNonBlocking);
        cudaStreamCreateWithFlags(&sC, cudaStreamNonBlocking);
        cudaEventCreateWithFlags(&eCvt, cudaEventDisableTiming);
        cudaEventCreateWithFlags(&eK, cudaEventDisableTiming);
        cudaEventCreateWithFlags(&eV, cudaEventDisableTiming);
        cudaEventCreateWithFlags(&eA, cudaEventDisableTiming);
        cudaEventCreateWithFlags(&eB, cudaEventDisableTiming);
        // Warm streams/events so lazy driver allocations happen NOW.
        cudaEventRecord(eCvt, 0);
        cudaStreamWaitEvent(sA, eCvt, 0);
        cudaStreamWaitEvent(sB, eCvt, 0);
        cudaStreamWaitEvent(sC, eCvt, 0);
        warm_kernel<<<1, 32, 0, sA>>>();
        warm_kernel<<<1, 32, 0, sB>>>();
        warm_kernel<<<1, 32, 0, sC>>>();
        cudaEventRecord(eA, sA); cudaEventRecord(eB, sB); cudaEventRecord(eV, sC);
        cudaStreamWaitEvent(0, eA, 0);
        cudaStreamWaitEvent(0, eB, 0);
        cudaStreamWaitEvent(0, eV, 0);
        cudaEventRecord(eK, 0);
        s_inited = true;
    }

    const float scale = 1.0f / sqrtf((float)D_DIM);
    const size_t nQE = (size_t)Q_DIM * E_DIM;   // 8M
    const size_t nDE = (size_t)D_DIM * E_DIM;   // 4M

    // ---- 1. cvt: proven 2-launch version (predicated selects, regs=17) ----
    cvt_split3_kernel<<<dim3((unsigned)(nQE / 1024), 3), 256>>>(
        query, key, value, q_hi, q_lo, k_hi, k_lo, v_hi, v_lo, nQE);
    cvt_split3_kernel<<<dim3((unsigned)(nDE / 1024), 3), 256>>>(
        Wq, Wk, Wv, Wq_hi, Wq_lo, Wk_hi, Wk_lo, Wv_hi, Wv_lo, nDE);
    cudaEventRecord(eCvt, 0);

    // ---- 2. projK on main stream (gates all scores; launched first) ----
    gemm_bf16x3<0><<<dim3(D_DIM / 128, S_DIM / 128), 256, SMEM_TOTAL>>>(
        k_hi, k_lo, Wk_hi, Wk_lo, bk, 1.0f, Kp_hi, Kp_lo, nullptr, E_DIM, D_DIM);
    cudaEventRecord(eK, 0);

    // ---- 3. projV on sC (records eV: out-GEMM gate) ----
    cudaStreamWaitEvent(sC, eCvt, 0);
    gemm_bf16x3<1><<<dim3(D_DIM / 128, S_DIM / 128), 256, SMEM_TOTAL, sC>>>(
        v_hi, v_lo, Wv_hi, Wv_lo, bv, 1.0f, VpT_hi, VpT_lo, nullptr, E_DIM, S_DIM);
    cudaEventRecord(eV, sC);

    // ---- 4. two chains (sA, sB), each sub-chunked into 2x1024 rows ----
    cudaStream_t chains[2] = {sA, sB};
    cudaEvent_t  eDone[2] = {eA, eB};
    for (int c = 0; c < 2; ++c) {
        cudaStream_t st = chains[c];
        const size_t ro = (size_t)c * CHUNK;

        cudaStreamWaitEvent(st, eCvt, 0);
        // projQ for the full chain (2048 rows)
        gemm_bf16x3<0><<<dim3(D_DIM / 128, CHUNK / 128), 256, SMEM_TOTAL, st>>>(
            q_hi + ro * E_DIM, q_lo + ro * E_DIM, Wq_hi, Wq_lo,
            bq, scale, Qp_hi + ro * D_DIM, Qp_lo + ro * D_DIM, nullptr, E_DIM, D_DIM);

        cudaStreamWaitEvent(st, eK, 0);
        cudaStreamWaitEvent(st, eV, 0);   // satisfied early; gates outs below

        for (int s = 0; s < 2; ++s) {
            const size_t so = ro + (size_t)s * SUB;
            // scores sub-chunk
            gemm_bf16x3<2><<<dim3(S_DIM / 128, SUB / 128), 256, SMEM_TOTAL, st>>>(
                Qp_hi + so * D_DIM, Qp_lo + so * D_DIM, Kp_hi, Kp_lo,
                nullptr, 1.0f, nullptr, nullptr, Sc + so * S_DIM, D_DIM, S_DIM);
            // softmax sub-chunk
            softmax_split_kernel<<<SUB, 256, 0, st>>>(
                Sc + so * S_DIM, P_hi + so * S_DIM, P_lo + so * S_DIM, S_DIM);
            // out sub-chunk (eV already waited on this stream)
            gemm_bf16x3<2><<<dim3(D_DIM / 128, SUB / 128), 256, SMEM_TOTAL, st>>>(
                P_hi + so * S_DIM, P_lo + so * S_DIM, VpT_hi, VpT_lo,
                nullptr, 1.0f, nullptr, nullptr, out + so * D_DIM, S_DIM, D_DIM);
        }
        cudaEventRecord(eDone[c], st);
    }

    // ---- 5. join back to main stream ----
    cudaStreamWaitEvent(0, eA, 0);
    cudaStreamWaitEvent(0, eB, 0);
}

// round 15
// speedup vs baseline: 1.1099x; 1.0236x over previous
#include <cuda_runtime.h>
#include <cuda_bf16.h>
#include <math.h>
#include <stdint.h>

#define S_DIM 4096
#define Q_DIM 4096
#define E_DIM 2048
#define D_DIM 2048
#define CHUNK 2048              /* rows per chain */

typedef __nv_bfloat16 bf16;

// ---------------------------------------------------------------------------
// Scratch (static device globals — no runtime allocation)
// ---------------------------------------------------------------------------
__device__ bf16 g_q_hi[(size_t)Q_DIM * E_DIM];
__device__ bf16 g_q_lo[(size_t)Q_DIM * E_DIM];
__device__ bf16 g_k_hi[(size_t)S_DIM * E_DIM];
__device__ bf16 g_k_lo[(size_t)S_DIM * E_DIM];
__device__ bf16 g_v_hi[(size_t)S_DIM * E_DIM];
__device__ bf16 g_v_lo[(size_t)S_DIM * E_DIM];
__device__ bf16 g_Wq_hi[(size_t)D_DIM * E_DIM];
__device__ bf16 g_Wq_lo[(size_t)D_DIM * E_DIM];
__device__ bf16 g_Wk_hi[(size_t)D_DIM * E_DIM];
__device__ bf16 g_Wk_lo[(size_t)D_DIM * E_DIM];
__device__ bf16 g_Wv_hi[(size_t)D_DIM * E_DIM];
__device__ bf16 g_Wv_lo[(size_t)D_DIM * E_DIM];
__device__ bf16 g_Qp_hi[(size_t)Q_DIM * D_DIM];
__device__ bf16 g_Qp_lo[(size_t)Q_DIM * D_DIM];
__device__ bf16 g_Kp_hi[(size_t)S_DIM * D_DIM];
__device__ bf16 g_Kp_lo[(size_t)S_DIM * D_DIM];
__device__ bf16 g_VpT_hi[(size_t)D_DIM * S_DIM];  // transposed [D, S]
__device__ bf16 g_VpT_lo[(size_t)D_DIM * S_DIM];
__device__ float g_Sc[(size_t)Q_DIM * S_DIM];
__device__ bf16 g_P_hi[(size_t)Q_DIM * S_DIM];
__device__ bf16 g_P_lo[(size_t)Q_DIM * S_DIM];

// ---------------------------------------------------------------------------
// helpers
// ---------------------------------------------------------------------------
__device__ __forceinline__ uint32_t smem_u32(const void* p) {
    uint32_t a;
    asm("{ .reg .u64 t; cvta.to.shared.u64 t, %1; cvt.u32.u64 %0, t; }"
        : "=r"(a) : "l"(p));
    return a;
}

__device__ __forceinline__ void cp_async16(uint32_t dst, const void* src) {
    asm volatile("cp.async.cg.shared.global [%0], [%1], 16;" :: "r"(dst), "l"(src));
}
#define CP_COMMIT()  asm volatile("cp.async.commit_group;" ::: "memory")
#define CP_WAIT_1()  asm volatile("cp.async.wait_group 1;" ::: "memory")

__device__ __forceinline__ void ldsm_x4(uint32_t& r0, uint32_t& r1, uint32_t& r2, uint32_t& r3,
                                        uint32_t addr) {
    asm volatile("ldmatrix.sync.aligned.m8n8.x4.shared.b16 {%0,%1,%2,%3}, [%4];"
                 : "=r"(r0), "=r"(r1), "=r"(r2), "=r"(r3) : "r"(addr));
}

__device__ __forceinline__ void mma_bf16(float* c, const uint32_t* a, const uint32_t* b) {
    asm volatile(
        "mma.sync.aligned.m16n8k16.row.col.f32.bf16.bf16.f32 "
        "{%0,%1,%2,%3}, {%4,%5,%6,%7}, {%8,%9}, {%0,%1,%2,%3};"
        : "+f"(c[0]), "+f"(c[1]), "+f"(c[2]), "+f"(c[3])
        : "r"(a[0]), "r"(a[1]), "r"(a[2]), "r"(a[3]), "r"(b[0]), "r"(b[1]));
}

__device__ __forceinline__ void split_bf16(float v, bf16& h, bf16& l) {
    h = __float2bfloat16(v);
    l = __float2bfloat16(v - __bfloat162float(h));
}

// warmup no-op (forces lazy per-stream driver resource allocation on call 1)
__global__ void warm_kernel() {}

// ---------------------------------------------------------------------------
// fp32 -> bf16 hi/lo split, 3 arrays per launch (ternary pointer selection
// compiles to predicated selects — NO local-memory pointer arrays).
// ---------------------------------------------------------------------------
__global__ __launch_bounds__(256) void cvt_split3_kernel(
    const float* __restrict__ x0, const float* __restrict__ x1, const float* __restrict__ x2,
    bf16* __restrict__ h0, bf16* __restrict__ l0,
    bf16* __restrict__ h1, bf16* __restrict__ l1,
    bf16* __restrict__ h2, bf16* __restrict__ l2, size_t n)
{
    const float* x = (blockIdx.y == 0) ? x0 : (blockIdx.y == 1) ? x1 : x2;
    bf16* hi = (blockIdx.y == 0) ? h0 : (blockIdx.y == 1) ? h1 : h2;
    bf16* lo = (blockIdx.y == 0) ? l0 : (blockIdx.y == 1) ? l1 : l2;
    size_t i = ((size_t)blockIdx.x * blockDim.x + threadIdx.x) * 4;
    if (i >= n) return;
    float4 v = *(const float4*)&x[i];
    bf16 a0, b0, a1, b1, a2, b2, a3, b3;
    split_bf16(v.x, a0, b0); split_bf16(v.y, a1, b1);
    split_bf16(v.z, a2, b2); split_bf16(v.w, a3, b3);
    __nv_bfloat162* ph = (__nv_bfloat162*)&hi[i];
    __nv_bfloat162* pl = (__nv_bfloat162*)&lo[i];
    ph[0] = __nv_bfloat162(a0, a1); ph[1] = __nv_bfloat162(a2, a3);
    pl[0] = __nv_bfloat162(b0, b1); pl[1] = __nv_bfloat162(b2, b3);
}

// ---------------------------------------------------------------------------
// bf16x3 GEMM via mma.sync: C[M,N] = (Ah+Al)[M,K] @ (Bh+Bl)[N,K]^T
// MODE 0: C = (acc + bias) * outscale -> Chi/Clo bf16, row-major [M, ldo]
// MODE 1: same, written transposed: Chi/Clo[col * ldo + row]
// MODE 2: C = acc -> Cf fp32 row-major [M, ldo]
// BM=BN=128, BK=32, 3 stages, 256 threads (8 warps 4x2), 2 CTAs/SM.
// ---------------------------------------------------------------------------
#define BK 32
#define NSTAGES 3
#define TILE_B 8192             /* 128 rows x 64 bytes */
#define STAGE_B (4 * TILE_B)    /* 32 KB */
#define SMEM_TOTAL (NSTAGES * STAGE_B)  /* 96 KB */

__device__ __forceinline__ uint32_t sw_off(int row, int chunk) {
    return (uint32_t)(row * 64 + ((chunk ^ ((row >> 1) & 3)) << 4));
}

template <int MODE>
__global__ void __launch_bounds__(256, 2) gemm_bf16x3(
    const bf16* __restrict__ Ah, const bf16* __restrict__ Al,
    const bf16* __restrict__ Bh, const bf16* __restrict__ Bl,
    const float* __restrict__ bias, float outscale,
    bf16* __restrict__ Chi, bf16* __restrict__ Clo, float* __restrict__ Cf,
    int K, int ldo)
{
    extern __shared__ __align__(1024) char smem[];
    const uint32_t sb = smem_u32(smem);
    const int tid  = threadIdx.x;
    const int wid  = tid >> 5;
    const int lane = tid & 31;
    const int bm   = blockIdx.y * 128;
    const int bn   = blockIdx.x * 128;
    const int KT   = K / BK;

    const int warp_m = wid & 3;
    const int warp_n = wid >> 2;
    const int m0 = warp_m * 32;
    const int n0 = warp_n * 64;

    auto load_stage = [&](int kt, int s) {
        const uint32_t sbase = sb + (uint32_t)s * STAGE_B;
        const bf16* srcs[4] = {Ah, Al, Bh, Bl};
#pragma unroll
        for (int t = 0; t < 4; ++t) {
            const int rowbase = (t < 2) ? bm : bn;
            const bf16* gsrc = srcs[t];
            const uint32_t tbase = sbase + (uint32_t)t * TILE_B;
#pragma unroll
            for (int i = 0; i < 2; ++i) {
                const int id = i * 256 + tid;
                const int r = id >> 2;
                const int c = id & 3;
                cp_async16(tbase + sw_off(r, c),
                           gsrc + (size_t)(rowbase + r) * K + kt * BK + c * 8);
            }
        }
        CP_COMMIT();
    };

    float acc[2][8][4];
#pragma unroll
    for (int i = 0; i < 2; ++i)
#pragma unroll
        for (int j = 0; j < 8; ++j)
#pragma unroll
            for (int q = 0; q < 4; ++q) acc[i][j][q] = 0.0f;

    const int a_row = m0 + (lane & 15);
    const int a_ch0 = lane >> 4;
    const int b_row = n0 + (lane & 7) + ((lane >> 4) << 3);
    const int b_ch0 = (lane >> 3) & 1;

    uint32_t a_h[2][4], a_l[2][4];
    uint32_t bA_h[4][2], bA_l[4][2];
    uint32_t bB_h[4][2], bB_l[4][2];

    auto ld_a = [&](uint32_t sbase, int ach) {
#pragma unroll
        for (int mt = 0; mt < 2; ++mt) {
            const uint32_t off = sw_off(a_row + mt * 16, ach);
            ldsm_x4(a_h[mt][0], a_h[mt][1], a_h[mt][2], a_h[mt][3], sbase + off);
            ldsm_x4(a_l[mt][0], a_l[mt][1], a_l[mt][2], a_l[mt][3], sbase + TILE_B + off);
        }
    };
    auto ld_b = [&](uint32_t sbase, int bch, int half, uint32_t (*bh)[2], uint32_t (*bl)[2]) {
        const uint32_t bh_base = sbase + 2 * TILE_B;
        const uint32_t bl_base = sbase + 3 * TILE_B;
#pragma unroll
        for (int jp = 0; jp < 2; ++jp) {
            const uint32_t off = sw_off(b_row + (half * 2 + jp) * 16, bch);
            ldsm_x4(bh[jp * 2][0], bh[jp * 2][1], bh[jp * 2 + 1][0], bh[jp * 2 + 1][1],
                    bh_base + off);
            ldsm_x4(bl[jp * 2][0], bl[jp * 2][1], bl[jp * 2 + 1][0], bl[jp * 2 + 1][1],
                    bl_base + off);
        }
    };
    auto mma24 = [&](int half, uint32_t (*bh)[2], uint32_t (*bl)[2]) {
#pragma unroll
        for (int mt = 0; mt < 2; ++mt)
#pragma unroll
            for (int j = 0; j < 4; ++j) mma_bf16(acc[mt][half * 4 + j], a_h[mt], bh[j]);
#pragma unroll
        for (int mt = 0; mt < 2; ++mt)
#pragma unroll
            for (int j = 0; j < 4; ++j) mma_bf16(acc[mt][half * 4 + j], a_h[mt], bl[j]);
#pragma unroll
        for (int mt = 0; mt < 2; ++mt)
#pragma unroll
            for (int j = 0; j < 4; ++j) mma_bf16(acc[mt][half * 4 + j], a_l[mt], bh[j]);
    };

    load_stage(0, 0);
    load_stage(1, 1);
    CP_WAIT_1();
    __syncthreads();
    {
        const uint32_t s0 = sb;
        ld_b(s0, b_ch0, 0, bA_h, bA_l);
        ld_b(s0, b_ch0, 1, bB_h, bB_l);
        ld_a(s0, a_ch0);
    }

#pragma unroll 1
    for (int kt = 0; kt < KT; ++kt) {
        const uint32_t scur = sb + (uint32_t)((kt % NSTAGES) * STAGE_B);

        if (kt + 2 < KT) load_stage(kt + 2, (kt + 2) % NSTAGES);
        else CP_COMMIT();

        mma24(0, bA_h, bA_l);
        ld_b(scur, 2 + b_ch0, 0, bA_h, bA_l);
        mma24(1, bB_h, bB_l);
        ld_b(scur, 2 + b_ch0, 1, bB_h, bB_l);
        ld_a(scur, 2 + a_ch0);

        CP_WAIT_1();
        __syncthreads();

        if (kt + 1 < KT) {
            const uint32_t snxt = sb + (uint32_t)(((kt + 1) % NSTAGES) * STAGE_B);
            mma24(0, bA_h, bA_l);
            ld_b(snxt, b_ch0, 0, bA_h, bA_l);
            mma24(1, bB_h, bB_l);
            ld_b(snxt, b_ch0, 1, bB_h, bB_l);
            ld_a(snxt, a_ch0);
        } else {
            mma24(0, bA_h, bA_l);
            mma24(1, bB_h, bB_l);
        }
    }

    const int er = lane >> 2;
    const int ec = (lane & 3) * 2;
#pragma unroll
    for (int mt = 0; mt < 2; ++mt) {
#pragma unroll
        for (int j = 0; j < 8; ++j) {
            const int row = bm + m0 + mt * 16 + er;
            const int col = bn + n0 + j * 8 + ec;
            float v0 = acc[mt][j][0], v1 = acc[mt][j][1];
            float v2 = acc[mt][j][2], v3 = acc[mt][j][3];
            if (MODE == 2) {
                *(float2*)&Cf[(size_t)row * ldo + col] = make_float2(v0, v1);
                *(float2*)&Cf[(size_t)(row + 8) * ldo + col] = make_float2(v2, v3);
            } else {
                const float b0 = bias[col], b1 = bias[col + 1];
                v0 = (v0 + b0) * outscale; v1 = (v1 + b1) * outscale;
                v2 = (v2 + b0) * outscale; v3 = (v3 + b1) * outscale;
                bf16 h0, l0, h1, l1, h2, l2, h3, l3;
                split_bf16(v0, h0, l0); split_bf16(v1, h1, l1);
                split_bf16(v2, h2, l2); split_bf16(v3, h3, l3);
                if (MODE == 0) {
                    *(__nv_bfloat162*)&Chi[(size_t)row * ldo + col] = __nv_bfloat162(h0, h1);
                    *(__nv_bfloat162*)&Clo[(size_t)row * ldo + col] = __nv_bfloat162(l0, l1);
                    *(__nv_bfloat162*)&Chi[(size_t)(row + 8) * ldo + col] = __nv_bfloat162(h2, h3);
                    *(__nv_bfloat162*)&Clo[(size_t)(row + 8) * ldo + col] = __nv_bfloat162(l2, l3);
                } else {  // MODE 1: transposed
                    Chi[(size_t)col * ldo + row] = h0;         Clo[(size_t)col * ldo + row] = l0;
                    Chi[(size_t)(col + 1) * ldo + row] = h1;   Clo[(size_t)(col + 1) * ldo + row] = l1;
                    Chi[(size_t)col * ldo + row + 8] = h2;     Clo[(size_t)col * ldo + row + 8] = l2;
                    Chi[(size_t)(col + 1) * ldo + row + 8] = h3; Clo[(size_t)(col + 1) * ldo + row + 8] = l3;
                }
            }
        }
    }
}

// ---------------------------------------------------------------------------
// Row softmax, single global pass: Sc (read once) -> P_hi/P_lo bf16.
// Row (16 KB) staged in dynamic shared memory; exp values kept in smem.
// Per-thread iteration order identical to the 3-pass version -> bit-identical.
// ---------------------------------------------------------------------------
__global__ __launch_bounds__(256) void softmax_split_kernel(
    const float* __restrict__ Sc, bf16* __restrict__ Phi,
    bf16* __restrict__ Plo, int cols)
{
    extern __shared__ float rowbuf[];           // cols floats (16 KB)
    __shared__ float red[32];
    const int row = blockIdx.x;
    const float* p = Sc + (size_t)row * cols;
    const int tid = threadIdx.x;
    const int lane = tid & 31;
    const int wid = tid >> 5;
    const int nwarp = blockDim.x >> 5;

    // --- load row to smem + max ---
    float m = -INFINITY;
    for (int i = tid * 4; i < cols; i += blockDim.x * 4) {
        float4 v = *(const float4*)&p[i];
        *(float4*)&rowbuf[i] = v;
        m = fmaxf(m, fmaxf(fmaxf(v.x, v.y), fmaxf(v.z, v.w)));
    }
#pragma unroll
    for (int o = 16; o > 0; o >>= 1) m = fmaxf(m, __shfl_xor_sync(0xffffffffu, m, o));
    if (lane == 0) red[wid] = m;
    __syncthreads();
    if (wid == 0) {
        float t = (lane < nwarp) ? red[lane] : -INFINITY;
#pragma unroll
        for (int o = 16; o > 0; o >>= 1) t = fmaxf(t, __shfl_xor_sync(0xffffffffu, t, o));
        if (lane == 0) red[0] = t;
    }
    __syncthreads();
    m = red[0];
    __syncthreads();

    // --- exp + sum (in smem) ---
    float s = 0.0f;
    for (int i = tid * 4; i < cols; i += blockDim.x * 4) {
        float4 v = *(const float4*)&rowbuf[i];
        v.x = __expf(v.x - m); v.y = __expf(v.y - m);
        v.z = __expf(v.z - m); v.w = __expf(v.w - m);
        s += v.x + v.y + v.z + v.w;
        *(float4*)&rowbuf[i] = v;
    }
#pragma unroll
    for (int o = 16; o > 0; o >>= 1) s += __shfl_xor_sync(0xffffffffu, s, o);
    if (lane == 0) red[wid] = s;
    __syncthreads();
    if (wid == 0) {
        float t = (lane < nwarp) ? red[lane] : 0.0f;
#pragma unroll
        for (int o = 16; o > 0; o >>= 1) t += __shfl_xor_sync(0xffffffffu, t, o);
        if (lane == 0) red[0] = t;
    }
    __syncthreads();
    const float inv = 1.0f / red[0];

    // --- normalize from smem + hi/lo split, write P only ---
    bf16* ph = Phi + (size_t)row * cols;
    bf16* pl = Plo + (size_t)row * cols;
    for (int i = tid * 4; i < cols; i += blockDim.x * 4) {
        float4 v = *(const float4*)&rowbuf[i];
        bf16 h0, l0, h1, l1, h2, l2, h3, l3;
        split_bf16(v.x * inv, h0, l0); split_bf16(v.y * inv, h1, l1);
        split_bf16(v.z * inv, h2, l2); split_bf16(v.w * inv, h3, l3);
        __nv_bfloat162* vh = (__nv_bfloat162*)&ph[i];
        __nv_bfloat162* vl = (__nv_bfloat162*)&pl[i];
        vh[0] = __nv_bfloat162(h0, h1); vh[1] = __nv_bfloat162(h2, h3);
        vl[0] = __nv_bfloat162(l0, l1); vl[1] = __nv_bfloat162(l2, l3);
    }
}

#define SOFTMAX_SMEM (S_DIM * (int)sizeof(float))   /* 16 KB */

// ---------------------------------------------------------------------------
// Host: exact round-10 topology (3 streams + 5 events, whole-chunk chains).
// Resources created once on call 1 (correctness run), reused during capture.
// ---------------------------------------------------------------------------
extern "C" void kernel_launch(void* const* d_in, const int* in_sizes, int n_in,
                              void* d_out, int out_size)
{
    const float* key   = (const float*)d_in[0];
    const float* value = (const float*)d_in[1];
    const float* query = (const float*)d_in[2];
    const float* Wk    = (const float*)d_in[3];
    const float* bk    = (const float*)d_in[4];
    const float* Wq    = (const float*)d_in[5];
    const float* bq    = (const float*)d_in[6];
    const float* Wv    = (const float*)d_in[7];
    const float* bv    = (const float*)d_in[8];
    float* out = (float*)d_out;

    void *q_hi_, *q_lo_, *k_hi_, *k_lo_, *v_hi_, *v_lo_;
    void *Wq_hi_, *Wq_lo_, *Wk_hi_, *Wk_lo_, *Wv_hi_, *Wv_lo_;
    void *Qp_hi_, *Qp_lo_, *Kp_hi_, *Kp_lo_, *VpT_hi_, *VpT_lo_;
    void *Sc_, *P_hi_, *P_lo_;
    cudaGetSymbolAddress(&q_hi_, g_q_hi);   cudaGetSymbolAddress(&q_lo_, g_q_lo);
    cudaGetSymbolAddress(&k_hi_, g_k_hi);   cudaGetSymbolAddress(&k_lo_, g_k_lo);
    cudaGetSymbolAddress(&v_hi_, g_v_hi);   cudaGetSymbolAddress(&v_lo_, g_v_lo);
    cudaGetSymbolAddress(&Wq_hi_, g_Wq_hi); cudaGetSymbolAddress(&Wq_lo_, g_Wq_lo);
    cudaGetSymbolAddress(&Wk_hi_, g_Wk_hi); cudaGetSymbolAddress(&Wk_lo_, g_Wk_lo);
    cudaGetSymbolAddress(&Wv_hi_, g_Wv_hi); cudaGetSymbolAddress(&Wv_lo_, g_Wv_lo);
    cudaGetSymbolAddress(&Qp_hi_, g_Qp_hi); cudaGetSymbolAddress(&Qp_lo_, g_Qp_lo);
    cudaGetSymbolAddress(&Kp_hi_, g_Kp_hi); cudaGetSymbolAddress(&Kp_lo_, g_Kp_lo);
    cudaGetSymbolAddress(&VpT_hi_, g_VpT_hi); cudaGetSymbolAddress(&VpT_lo_, g_VpT_lo);
    cudaGetSymbolAddress(&Sc_, g_Sc);
    cudaGetSymbolAddress(&P_hi_, g_P_hi);   cudaGetSymbolAddress(&P_lo_, g_P_lo);

    bf16 *q_hi = (bf16*)q_hi_, *q_lo = (bf16*)q_lo_;
    bf16 *k_hi = (bf16*)k_hi_, *k_lo = (bf16*)k_lo_;
    bf16 *v_hi = (bf16*)v_hi_, *v_lo = (bf16*)v_lo_;
    bf16 *Wq_hi = (bf16*)Wq_hi_, *Wq_lo = (bf16*)Wq_lo_;
    bf16 *Wk_hi = (bf16*)Wk_hi_, *Wk_lo = (bf16*)Wk_lo_;
    bf16 *Wv_hi = (bf16*)Wv_hi_, *Wv_lo = (bf16*)Wv_lo_;
    bf16 *Qp_hi = (bf16*)Qp_hi_, *Qp_lo = (bf16*)Qp_lo_;
    bf16 *Kp_hi = (bf16*)Kp_hi_, *Kp_lo = (bf16*)Kp_lo_;
    bf16 *VpT_hi = (bf16*)VpT_hi_, *VpT_lo = (bf16*)VpT_lo_;
    float *Sc = (float*)Sc_;
    bf16 *P_hi = (bf16*)P_hi_, *P_lo = (bf16*)P_lo_;

    // One-time resource setup (correctness run); reused during capture.
    static bool s_inited = false;
    static cudaStream_t sA, sB, sC;
    static cudaEvent_t eCvt, eK, eV, eA, eB;
    if (!s_inited) {
        cudaFuncSetAttribute(gemm_bf16x3<0>, cudaFuncAttributeMaxDynamicSharedMemorySize, SMEM_TOTAL);
        cudaFuncSetAttribute(gemm_bf16x3<1>, cudaFuncAttributeMaxDynamicSharedMemorySize, SMEM_TOTAL);
        cudaFuncSetAttribute(gemm_bf16x3<2>, cudaFuncAttributeMaxDynamicSharedMemorySize, SMEM_TOTAL);
        cudaStreamCreateWithFlags(&sA, cudaStreamNonBlocking);
        cudaStreamCreateWithFlags(&sB, cudaStreamNonBlocking);
        cudaStreamCreateWithFlags(&sC, cudaStreamNonBlocking);
        cudaEventCreateWithFlags(&eCvt, cudaEventDisableTiming);
        cudaEventCreateWithFlags(&eK, cudaEventDisableTiming);
        cudaEventCreateWithFlags(&eV, cudaEventDisableTiming);
        cudaEventCreateWithFlags(&eA, cudaEventDisableTiming);
        cudaEventCreateWithFlags(&eB, cudaEventDisableTiming);
        // Warm streams/events so lazy driver allocations happen NOW.
        cudaEventRecord(eCvt, 0);
        cudaStreamWaitEvent(sA, eCvt, 0);
        cudaStreamWaitEvent(sB, eCvt, 0);
        cudaStreamWaitEvent(sC, eCvt, 0);
        warm_kernel<<<1, 32, 0, sA>>>();
        warm_kernel<<<1, 32, 0, sB>>>();
        warm_kernel<<<1, 32, 0, sC>>>();
        cudaEventRecord(eA, sA); cudaEventRecord(eB, sB); cudaEventRecord(eV, sC);
        cudaStreamWaitEvent(0, eA, 0);
        cudaStreamWaitEvent(0, eB, 0);
        cudaStreamWaitEvent(0, eV, 0);
        cudaEventRecord(eK, 0);
        s_inited = true;
    }

    const float scale = 1.0f / sqrtf((float)D_DIM);
    const size_t nQE = (size_t)Q_DIM * E_DIM;   // 8M
    const size_t nDE = (size_t)D_DIM * E_DIM;   // 4M

    // ---- 1. cvt (2 launches, main stream) ----
    cvt_split3_kernel<<<dim3((unsigned)(nQE / 1024), 3), 256>>>(
        query, key, value, q_hi, q_lo, k_hi, k_lo, v_hi, v_lo, nQE);
    cvt_split3_kernel<<<dim3((unsigned)(nDE / 1024), 3), 256>>>(
        Wq, Wk, Wv, Wq_hi, Wq_lo, Wk_hi, Wk_lo, Wv_hi, Wv_lo, nDE);
    cudaEventRecord(eCvt, 0);

    // ---- 2. projK on main stream (gates all scores; launched first) ----
    gemm_bf16x3<0><<<dim3(D_DIM / 128, S_DIM / 128), 256, SMEM_TOTAL>>>(
        k_hi, k_lo, Wk_hi, Wk_lo, bk, 1.0f, Kp_hi, Kp_lo, nullptr, E_DIM, D_DIM);
    cudaEventRecord(eK, 0);

    // ---- 3. projV on sC (records eV: out-GEMM gate) ----
    cudaStreamWaitEvent(sC, eCvt, 0);
    gemm_bf16x3<1><<<dim3(D_DIM / 128, S_DIM / 128), 256, SMEM_TOTAL, sC>>>(
        v_hi, v_lo, Wv_hi, Wv_lo, bv, 1.0f, VpT_hi, VpT_lo, nullptr, E_DIM, S_DIM);
    cudaEventRecord(eV, sC);

    // ---- 4. two whole-chunk chains (sA, sB) ----
    cudaStream_t chains[2] = {sA, sB};
    cudaEvent_t  eDone[2] = {eA, eB};
    for (int c = 0; c < 2; ++c) {
        cudaStream_t st = chains[c];
        const size_t ro = (size_t)c * CHUNK;

        cudaStreamWaitEvent(st, eCvt, 0);
        gemm_bf16x3<0><<<dim3(D_DIM / 128, CHUNK / 128), 256, SMEM_TOTAL, st>>>(
            q_hi + ro * E_DIM, q_lo + ro * E_DIM, Wq_hi, Wq_lo,
            bq, scale, Qp_hi + ro * D_DIM, Qp_lo + ro * D_DIM, nullptr, E_DIM, D_DIM);

        cudaStreamWaitEvent(st, eK, 0);
        gemm_bf16x3<2><<<dim3(S_DIM / 128, CHUNK / 128), 256, SMEM_TOTAL, st>>>(
            Qp_hi + ro * D_DIM, Qp_lo + ro * D_DIM, Kp_hi, Kp_lo,
            nullptr, 1.0f, nullptr, nullptr, Sc + ro * S_DIM, D_DIM, S_DIM);

        softmax_split_kernel<<<CHUNK, 256, SOFTMAX_SMEM, st>>>(
            Sc + ro * S_DIM, P_hi + ro * S_DIM, P_lo + ro * S_DIM, S_DIM);

        cudaStreamWaitEvent(st, eV, 0);
        gemm_bf16x3<2><<<dim3(D_DIM / 128, CHUNK / 128), 256, SMEM_TOTAL, st>>>(
            P_hi + ro * S_DIM, P_lo + ro * S_DIM, VpT_hi, VpT_lo,
            nullptr, 1.0f, nullptr, nullptr, out + ro * D_DIM, S_DIM, D_DIM);
        cudaEventRecord(eDone[c], st);
    }

    // ---- 5. join back to main stream ----
    cudaStreamWaitEvent(0, eA, 0);
    cudaStreamWaitEvent(0, eB, 0);
}